// round 14
// baseline (speedup 1.0000x reference)
#include <cuda_runtime.h>
#include <cstdint>

// Problem constants
#define BSZ     256
#define IDIM    182
#define TSTEPS  2000
#define H0LEN   1024         // half 0: t in [0,1024)    -- 128B-aligned rows
#define H1LEN   976          // half 1: t in [1024,2000) -- base offset 4096B, aligned
#define OCH     2
#define CHUNK   4            // steps per thread in scan phase
#define GRID    (BSZ * 2)    // CTA 2b+h: batch b, t-half h

// TMA pipeline shape
#define RPG       4                         // input rows per pipeline group
#define NST       3                         // pipeline stages
#define NG        ((IDIM + RPG - 1) / RPG)  // 46 groups (last has 2 rows)
#define ROWPITCH  4096                      // staged row pitch (bytes)
#define STAGEB    (RPG * ROWPITCH)          // 16384 B per stage

// dynamic SMEM layout (bytes)
#define SM_SBUF   0
#define SM_W      (NST * STAGEB)            // 49152
#define SM_MBAR   (SM_W + 1472)             // W = 2*182*4 = 1456, pad to 1472
#define SM_TS     (SM_MBAR + 64)            // 6 mbarriers (48 B), pad to 64
#define SM_ES     (SM_TS + 128)
#define SM_BND    (SM_ES + 128)
#define SM_TOTAL  (SM_BND + 16)             // 50960

// boundary handoff: half-0 final state (syn0,mem0,syn1,mem1) + flag per batch
__device__ float g_state[BSZ][4];
__device__ volatile unsigned g_flag[BSZ];   // zero-init; consumer resets -> replay-safe

// ---- PTX helpers -----------------------------------------------------------
__device__ __forceinline__ uint32_t smem_u32(const void* p) {
    uint32_t a;
    asm("{ .reg .u64 t; cvta.to.shared.u64 t, %1; cvt.u32.u64 %0, t; }"
        : "=r"(a) : "l"(p));
    return a;
}
__device__ __forceinline__ void mbar_init(uint32_t mb, uint32_t cnt) {
    asm volatile("mbarrier.init.shared.b64 [%0], %1;" :: "r"(mb), "r"(cnt) : "memory");
}
__device__ __forceinline__ void mbar_expect_tx(uint32_t mb, uint32_t bytes) {
    asm volatile("mbarrier.arrive.expect_tx.shared.b64 _, [%0], %1;"
                 :: "r"(mb), "r"(bytes) : "memory");
}
__device__ __forceinline__ void mbar_arrive(uint32_t mb) {
    asm volatile("mbarrier.arrive.shared.b64 _, [%0];" :: "r"(mb) : "memory");
}
__device__ __forceinline__ void mbar_wait(uint32_t mb, uint32_t ph) {
    asm volatile(
        "{\n\t.reg .pred P;\n\t"
        "WL_%=:\n\t"
        "mbarrier.try_wait.parity.acquire.cta.shared::cta.b64 P, [%0], %1, 0x989680;\n\t"
        "@P bra.uni WD_%=;\n\t"
        "bra.uni WL_%=;\n\t"
        "WD_%=:\n\t}"
        :: "r"(mb), "r"(ph) : "memory");
}
__device__ __forceinline__ void bulk_g2s(uint32_t dst, const void* src,
                                         uint32_t bytes, uint32_t mb) {
    asm volatile(
        "cp.async.bulk.shared::cluster.global.mbarrier::complete_tx::bytes "
        "[%0], [%1], %2, [%3];"
        :: "r"(dst), "l"(src), "r"(bytes), "r"(mb) : "memory");
}

// ---------------------------------------------------------------------------
// Fully fused kernel: TMA-pipelined GEMM with DECOUPLED warps (full/empty
// mbarrier pairs instead of per-group __syncthreads) + register-resident
// chunked scan.
//   full[s]:  tx-barrier (count 1 + expect_tx), completed by TMA delivery
//   empty[s]: count-256 barrier; every thread arrives after consuming stage s;
//             thread 0 waits its completion before reissuing the slot.
//   Warps run ahead independently; per-group straggler re-alignment is gone.
// Scan: syn_t = a*syn+c ; mem_t = m*mem+syn, log-depth, currents in registers.
// Half 1 seeds its composition with half 0's boundary state (affine scan).
// Spin safety: __launch_bounds__(256,4) + 51KB smem -> 4 CTAs/SM -> all 512
// CTAs co-resident (592 slots); producer never blocks.
// ---------------------------------------------------------------------------
__global__ __launch_bounds__(256, 4)
void snn_fused_kernel(const float* __restrict__ inp,   // [B, I, T]
                      const float* __restrict__ W,     // [O, I]
                      const float* __restrict__ bias,  // [O]
                      const float* __restrict__ alpha,
                      const float* __restrict__ beta,
                      float* __restrict__ out)         // [B, T, O]
{
    extern __shared__ char smem[];
    float* Wsh = (float*)(smem + SM_W);     // [2*182] flat: o*IDIM + i
    float* ts  = (float*)(smem + SM_TS);    // [o][w][2] -> o*16 + w*2 + k
    float* es  = (float*)(smem + SM_ES);
    float* bnd = (float*)(smem + SM_BND);

    const uint32_t smb    = smem_u32(smem);
    const uint32_t sbuf0  = smb + SM_SBUF;
    const uint32_t full0  = smb + SM_MBAR;        // full[s]  = full0  + s*8
    const uint32_t empty0 = smb + SM_MBAR + 24;   // empty[s] = empty0 + s*8

    const int tid = threadIdx.x;
    const int b   = blockIdx.x >> 1;
    const int h   = blockIdx.x & 1;

    const int tbase = h ? H0LEN : 0;
    const int nch   = h ? (H1LEN / 4) : (H0LEN / 4);   // 244 or 256 live threads
    const bool gl   = (tid < nch);
    const uint32_t rowbytes = (h ? H1LEN : H0LEN) * 4; // 3904 / 4096 (both %16==0)

    const float* rowsrc = inp + (size_t)b * IDIM * TSTEPS + tbase;

    // ---- pipeline init + prologue issue (before W load: stream starts now) --
    if (tid == 0) {
        #pragma unroll
        for (int s = 0; s < NST; s++) {
            mbar_init(full0  + s * 8, 1);
            mbar_init(empty0 + s * 8, 256);
        }
    }
    __syncthreads();
    asm volatile("fence.proxy.async.shared::cta;" ::: "memory");
    if (tid == 0) {
        #pragma unroll
        for (int g = 0; g < NST; g++) {
            const int i0 = g * RPG;
            const int rows = (i0 + RPG <= IDIM) ? RPG : (IDIM - i0);
            const uint32_t mb = full0 + g * 8;
            mbar_expect_tx(mb, (uint32_t)rows * rowbytes);
            for (int r = 0; r < rows; r++)
                bulk_g2s(sbuf0 + g * STAGEB + r * ROWPITCH,
                         rowsrc + (size_t)(i0 + r) * TSTEPS, rowbytes, mb);
        }
    }
    for (int k = tid; k < OCH * IDIM; k += 256)
        Wsh[k] = W[k];
    __syncthreads();

    // ======================= phase 1: pipelined GEMM (decoupled) =============
    float4 acc0 = make_float4(0.f, 0.f, 0.f, 0.f);
    float4 acc1 = make_float4(0.f, 0.f, 0.f, 0.f);

    for (int g = 0; g < NG; g++) {
        const int slot    = g % NST;
        const uint32_t par = (uint32_t)((g / NST) & 1);

        mbar_wait(full0 + slot * 8, par);       // stage delivered?

        if (gl) {
            const int i0 = g * RPG;
            const char* base = smem + SM_SBUF + slot * STAGEB + tid * 16;
            #pragma unroll
            for (int r = 0; r < RPG; r++) {
                if (i0 + r < IDIM) {
                    const float4 x = *reinterpret_cast<const float4*>(base + r * ROWPITCH);
                    const float w0 = Wsh[i0 + r];
                    const float w1 = Wsh[IDIM + i0 + r];
                    acc0.x = fmaf(w0, x.x, acc0.x); acc0.y = fmaf(w0, x.y, acc0.y);
                    acc0.z = fmaf(w0, x.z, acc0.z); acc0.w = fmaf(w0, x.w, acc0.w);
                    acc1.x = fmaf(w1, x.x, acc1.x); acc1.y = fmaf(w1, x.y, acc1.y);
                    acc1.z = fmaf(w1, x.z, acc1.z); acc1.w = fmaf(w1, x.w, acc1.w);
                }
            }
        }
        mbar_arrive(empty0 + slot * 8);         // this thread is done with stage

        const int g2 = g + NST;
        if (tid == 0 && g2 < NG) {
            // all 256 arrivals for this use (completion g/NST + 1, phase g/NST)
            mbar_wait(empty0 + slot * 8, par);
            const int i0 = g2 * RPG;
            const int rows = (i0 + RPG <= IDIM) ? RPG : (IDIM - i0);
            const uint32_t mb = full0 + slot * 8;
            mbar_expect_tx(mb, (uint32_t)rows * rowbytes);
            for (int r = 0; r < rows; r++)
                bulk_g2s(sbuf0 + slot * STAGEB + r * ROWPITCH,
                         rowsrc + (size_t)(i0 + r) * TSTEPS, rowbytes, mb);
        }
    }

    if (gl) {
        const float b0 = bias[0], b1 = bias[1];
        acc0.x += b0; acc0.y += b0; acc0.z += b0; acc0.w += b0;
        acc1.x += b1; acc1.y += b1; acc1.z += b1; acc1.w += b1;
    }

    // ======================= phase 2: scan (register currents) ==============
    const int j    = tid;
    const int lane = j & 31;
    const int w    = j >> 5;

    float a[OCH], m[OCH];
    a[0] = __saturatef(alpha[0]); a[1] = __saturatef(alpha[1]);
    m[0] = __saturatef(beta[0]);  m[1] = __saturatef(beta[1]);

    float c[OCH][CHUNK];
    c[0][0] = acc0.x; c[0][1] = acc0.y; c[0][2] = acc0.z; c[0][3] = acc0.w;
    c[1][0] = acc1.x; c[1][1] = acc1.y; c[1][2] = acc1.z; c[1][3] = acc1.w;

    float vs[OCH], vm[OCH];
    #pragma unroll
    for (int o = 0; o < OCH; o++) {
        float s = 0.f, q = 0.f;
        #pragma unroll
        for (int k = 0; k < CHUNK; k++) {
            s = fmaf(a[o], s, c[o][k]);
            q = fmaf(m[o], q, s);
        }
        vs[o] = s; vm[o] = q;
    }

    // P = M^CHUNK per channel:  M = [[a,0],[a,m]], M^k = [[A,0],[C,B]]
    float PA[OCH], PB[OCH], PC[OCH];
    #pragma unroll
    for (int o = 0; o < OCH; o++) {
        float A = 1.f, B = 1.f, C = 0.f;
        #pragma unroll
        for (int k = 0; k < CHUNK; k++) {
            A = a[o] * A;
            C = fmaf(m[o], C, A);
            B = m[o] * B;
        }
        PA[o] = A; PB[o] = B; PC[o] = C;
    }

    // Kogge-Stone intra-warp scan; build L = P^lane on the fly
    float LA[OCH] = {1.f, 1.f}, LB[OCH] = {1.f, 1.f}, LC[OCH] = {0.f, 0.f};
    #pragma unroll
    for (int d = 1; d <= 16; d <<= 1) {
        #pragma unroll
        for (int o = 0; o < OCH; o++) {
            if (lane & d) {
                const float nA = LA[o] * PA[o];
                const float nB = LB[o] * PB[o];
                const float nC = fmaf(LC[o], PA[o], LB[o] * PC[o]);
                LA[o] = nA; LB[o] = nB; LC[o] = nC;
            }
        }
        #pragma unroll
        for (int o = 0; o < OCH; o++) {
            const float ws = __shfl_up_sync(0xffffffffu, vs[o], d);
            const float wq = __shfl_up_sync(0xffffffffu, vm[o], d);
            if (lane >= d) {
                vm[o] = fmaf(PC[o], ws, fmaf(PB[o], wq, vm[o]));
                vs[o] = fmaf(PA[o], ws, vs[o]);
            }
        }
        #pragma unroll
        for (int o = 0; o < OCH; o++) {
            PC[o] = PC[o] * (PA[o] + PB[o]);
            PA[o] = PA[o] * PA[o];
            PB[o] = PB[o] * PB[o];
        }
    }
    // P now holds P^32 (warp-span matrix)

    if (lane == 31) {
        #pragma unroll
        for (int o = 0; o < OCH; o++) {
            ts[o * 16 + w * 2 + 0] = vs[o];
            ts[o * 16 + w * 2 + 1] = vm[o];
        }
    }

    // boundary seed: half 0 -> zeros; half 1 -> wait for half 0's final state
    if (tid == 0) {
        if (h == 1) {
            while (g_flag[b] == 0u) { /* brief spin; producer co-resident */ }
            __threadfence();            // acquire
            bnd[0] = g_state[b][0];
            bnd[1] = g_state[b][1];
            bnd[2] = g_state[b][2];
            bnd[3] = g_state[b][3];
            g_flag[b] = 0u;             // reset for next graph replay
        } else {
            bnd[0] = 0.f; bnd[1] = 0.f; bnd[2] = 0.f; bnd[3] = 0.f;
        }
    }
    __syncthreads();

    // serial composition over 8 warp totals, seeded with boundary state.
    // h=0: the final (Ss,Sm) is exactly the state after t=1023 -> publish now.
    if (j < OCH) {
        const int o = j;
        float Ss = bnd[2 * o + 0];
        float Sm = bnd[2 * o + 1];
        #pragma unroll
        for (int k = 0; k < 8; k++) {
            es[o * 16 + k * 2 + 0] = Ss;
            es[o * 16 + k * 2 + 1] = Sm;
            const float tsv = ts[o * 16 + k * 2 + 0];
            const float tmv = ts[o * 16 + k * 2 + 1];
            const float ns = fmaf(PA[o], Ss, tsv);
            const float nm = fmaf(PC[o], Ss, fmaf(PB[o], Sm, tmv));
            Ss = ns; Sm = nm;
        }
        if (h == 0) {
            g_state[b][2 * o + 0] = Ss;
            g_state[b][2 * o + 1] = Sm;
            __threadfence();            // release state pair
        }
    }
    __syncthreads();
    if (h == 0 && tid == 0) {
        __threadfence();
        g_flag[b] = 1u;                 // release flag after both pairs
    }

    // replay with true prefix state; streaming float4 stores
    if (gl) {
        float pre_s[OCH], pre_m[OCH];
        #pragma unroll
        for (int o = 0; o < OCH; o++) {
            float Xs = __shfl_up_sync(0xffffffffu, vs[o], 1);
            float Xm = __shfl_up_sync(0xffffffffu, vm[o], 1);
            if (lane == 0) { Xs = 0.f; Xm = 0.f; }
            const float esv = es[o * 16 + w * 2 + 0];
            const float emv = es[o * 16 + w * 2 + 1];
            pre_s[o] = fmaf(LA[o], esv, Xs);
            pre_m[o] = fmaf(LC[o], esv, fmaf(LB[o], emv, Xm));
        }
        float s0 = pre_s[0], q0 = pre_m[0];
        float s1 = pre_s[1], q1 = pre_m[1];

        float r[2 * CHUNK];
        #pragma unroll
        for (int k = 0; k < CHUNK; k++) {
            s0 = fmaf(a[0], s0, c[0][k]); q0 = fmaf(m[0], q0, s0);
            s1 = fmaf(a[1], s1, c[1][k]); q1 = fmaf(m[1], q1, s1);
            r[2 * k + 0] = q0;
            r[2 * k + 1] = q1;
        }

        float4* ob = reinterpret_cast<float4*>(out + ((size_t)b * TSTEPS + tbase + j * 4) * OCH);
        __stcs(ob + 0, make_float4(r[0], r[1], r[2], r[3]));
        __stcs(ob + 1, make_float4(r[4], r[5], r[6], r[7]));
    }
}

extern "C" void kernel_launch(void* const* d_in, const int* in_sizes, int n_in,
                              void* d_out, int out_size)
{
    const float* inp   = (const float*)d_in[0]; // [256,182,2000]
    const float* W     = (const float*)d_in[1]; // [2,182]
    const float* bias  = (const float*)d_in[2]; // [2]
    const float* alpha = (const float*)d_in[3]; // [2]
    const float* beta  = (const float*)d_in[4]; // [2]
    float* out = (float*)d_out;                 // [256,2000,2]

    cudaFuncSetAttribute(snn_fused_kernel,
                         cudaFuncAttributeMaxDynamicSharedMemorySize, SM_TOTAL);
    snn_fused_kernel<<<GRID, 256, SM_TOTAL>>>(inp, W, bias, alpha, beta, out);
}